// round 13
// baseline (speedup 1.0000x reference)
#include <cuda_runtime.h>
#include <cuda_bf16.h>
#include <cuda_fp16.h>
#include <cstdint>

#define NN 40000
#define DD 128
#define EE 640000
#define SCAN_BLKS ((NN + 255) / 256)   // 157

// ---------------- device scratch (static, no allocation) ----------------
// INVARIANT: g_cnt, g_colsum, g_colsq are all-zero at kernel_launch entry.
// (zero-initialized statics; every full execution restores them at end-of-use)
__device__ float    g_h  [(size_t)NN * DD];  // h = (1+eps)*x + agg
__device__ float    g_h1 [(size_t)NN * DD];  // h @ W1.T (b1 dropped: BN shift-invariant)
__device__ uint32_t g_xh [(size_t)NN * 64];  // fp16 copy of x (half2-packed)
__device__ int      g_csr[EE];
__device__ int      g_cnt[NN];
__device__ int      g_off[NN + 1];
__device__ int      g_cur[NN];
__device__ int      g_bsum[SCAN_BLKS];
__device__ float    g_colsum[DD];
__device__ float    g_colsq [DD];
__device__ float    g_scale [DD];
__device__ float    g_shift [DD];
// flat bf16 images per W: hi = u32[0:8192), lo = u32[8192:16384)  ([row][64] u32)
__device__ uint32_t g_w1img[16384];
__device__ uint32_t g_w2img[16384];

__device__ __forceinline__ uint32_t bf2_bits(float a, float b) {
    __nv_bfloat162 t = __floats2bfloat162_rn(a, b);
    return *reinterpret_cast<uint32_t*>(&t);
}
__device__ __forceinline__ uint32_t h2_bits(float a, float b) {
    __half2 t = __floats2half2_rn(a, b);
    return *reinterpret_cast<uint32_t*>(&t);
}

// ---------------- prep: x->fp16 + W split + dst histogram ----------------
// g_cnt is zero on entry (see invariant), so hist atomics can run directly.
__global__ __launch_bounds__(256)
void prep_kernel(const float* __restrict__ x,
                 const float* __restrict__ W1,
                 const float* __restrict__ W2,
                 const int*   __restrict__ dst) {
    int i = blockIdx.x * 256 + threadIdx.x;

    // x -> fp16 (NN*32 float4 quads)
    if (i < NN * 32) {
        int row = i >> 5, q = i & 31;
        float4 v = *(const float4*)(x + (size_t)row * DD + q * 4);
        *reinterpret_cast<uint2*>(g_xh + row * 64 + q * 2) =
            make_uint2(h2_bits(v.x, v.y), h2_bits(v.z, v.w));
    }

    // dst histogram (EE/4 = 160000 int4 quads)
    if (i < EE / 4) {
        int4 d = *(const int4*)(dst + i * 4);
        atomicAdd(&g_cnt[d.x], 1);
        atomicAdd(&g_cnt[d.y], 1);
        atomicAdd(&g_cnt[d.z], 1);
        atomicAdd(&g_cnt[d.w], 1);
    }

    // W split (8192 float4 quads across both W's)
    if (i < 8192) {
        const float* W = (i < 4096) ? W1 : W2;
        uint32_t*  img = (i < 4096) ? g_w1img : g_w2img;
        int j = i & 4095;
        int row = j >> 5, q = j & 31;
        float4 v = *(const float4*)(W + (size_t)row * DD + q * 4);
        uint32_t h01 = bf2_bits(v.x, v.y);
        uint32_t h23 = bf2_bits(v.z, v.w);
        __nv_bfloat162* hp01 = reinterpret_cast<__nv_bfloat162*>(&h01);
        __nv_bfloat162* hp23 = reinterpret_cast<__nv_bfloat162*>(&h23);
        float l0 = v.x - __bfloat162float(hp01->x);
        float l1 = v.y - __bfloat162float(hp01->y);
        float l2 = v.z - __bfloat162float(hp23->x);
        float l3 = v.w - __bfloat162float(hp23->y);
        *reinterpret_cast<uint2*>(img + row * 64 + 2 * q) = make_uint2(h01, h23);
        *reinterpret_cast<uint2*>(img + 8192 + row * 64 + 2 * q) =
            make_uint2(bf2_bits(l0, l1), bf2_bits(l2, l3));
    }
}

// ---------------- K2a: per-block reduce of cnt ----------------
__global__ __launch_bounds__(256)
void scan_reduce_kernel() {
    int i = blockIdx.x * 256 + threadIdx.x;
    int v = (i < NN) ? g_cnt[i] : 0;
    #pragma unroll
    for (int o = 16; o > 0; o >>= 1) v += __shfl_down_sync(0xffffffffu, v, o);
    __shared__ int ws[8];
    if ((threadIdx.x & 31) == 0) ws[threadIdx.x >> 5] = v;
    __syncthreads();
    if (threadIdx.x < 8) {
        int s = ws[threadIdx.x];
        #pragma unroll
        for (int o = 4; o > 0; o >>= 1) s += __shfl_down_sync(0xffu, s, o);
        if (threadIdx.x == 0) g_bsum[blockIdx.x] = s;
    }
}

// ---------------- K2b: final scan (each block redundantly scans g_bsum) ----
// Also resets g_cnt to zero (end-of-use) to maintain the entry invariant.
__global__ __launch_bounds__(256)
void scan_final_kernel() {
    __shared__ int sh[256];
    __shared__ int wtot[8];
    int t = threadIdx.x;

    // redundant in-block scan of the 157 block sums (L2-hot)
    int bs = (t < SCAN_BLKS) ? g_bsum[t] : 0;
    sh[t] = bs;
    __syncthreads();
    #pragma unroll
    for (int o = 1; o < 256; o <<= 1) {
        int u = (t >= o) ? sh[t - o] : 0;
        __syncthreads();
        sh[t] += u;
        __syncthreads();
    }
    int myboff = (blockIdx.x == 0) ? 0 : sh[blockIdx.x - 1];   // exclusive

    // per-element scan within this block's 256 elements
    int i = blockIdx.x * 256 + t;
    int lane = t & 31, wrp = t >> 5;
    int v = (i < NN) ? g_cnt[i] : 0;
    int inc = v;
    #pragma unroll
    for (int o = 1; o < 32; o <<= 1) {
        int u = __shfl_up_sync(0xffffffffu, inc, o);
        if (lane >= o) inc += u;
    }
    if (lane == 31) wtot[wrp] = inc;
    __syncthreads();
    if (t < 8) {
        int s = wtot[t];
        #pragma unroll
        for (int o = 1; o < 8; o <<= 1) {
            int u = __shfl_up_sync(0xffu, s, o);
            if (t >= o) s += u;
        }
        wtot[t] = s - wtot[t];   // exclusive warp offsets
    }
    __syncthreads();
    int off = myboff + wtot[wrp] + (inc - v);
    if (i < NN) {
        g_off[i] = off;
        g_cur[i] = off;
        g_cnt[i] = 0;            // restore invariant for next call
    }
    if (blockIdx.x == 0 && t == 0) g_off[NN] = EE;
}

// ---------------- K3: scatter edges into CSR ----------------
__global__ void scatter_kernel(const int* __restrict__ src,
                               const int* __restrict__ dst) {
    int e = (blockIdx.x * blockDim.x + threadIdx.x) * 4;
    if (e + 3 < EE) {
        int4 d = *(const int4*)(dst + e);
        int4 s = *(const int4*)(src + e);
        g_csr[atomicAdd(&g_cur[d.x], 1)] = s.x;
        g_csr[atomicAdd(&g_cur[d.y], 1)] = s.y;
        g_csr[atomicAdd(&g_cur[d.z], 1)] = s.z;
        g_csr[atomicAdd(&g_cur[d.w], 1)] = s.w;
    }
}

// ---------------- K4: aggregate (one warp per row, fp16 gather) ----------------
__global__ __launch_bounds__(256)
void agg_kernel(const float* __restrict__ x, const float* __restrict__ eps) {
    int gt   = blockIdx.x * blockDim.x + threadIdx.x;
    int row  = gt >> 5;
    int lane = gt & 31;
    if (row >= NN) return;

    float s0 = 1.0f + eps[0];
    float4 a = *((const float4*)(x + (size_t)row * DD) + lane);
    a.x *= s0; a.y *= s0; a.z *= s0; a.w *= s0;

    int jb = g_off[row], je = g_off[row + 1];
    for (int j0 = jb; j0 < je; j0 += 32) {
        int rem = je - j0;
        int myidx = (lane < rem) ? g_csr[j0 + lane] : 0;
        int cnt = rem < 32 ? rem : 32;
        for (int t = 0; t < cnt; ++t) {
            int sidx = __shfl_sync(0xffffffffu, myidx, t);
            uint2 hv = *((const uint2*)(g_xh + (size_t)sidx * 64) + lane);
            float2 f0 = __half22float2(*reinterpret_cast<__half2*>(&hv.x));
            float2 f1 = __half22float2(*reinterpret_cast<__half2*>(&hv.y));
            a.x += fmaxf(f0.x, 0.f);
            a.y += fmaxf(f0.y, 0.f);
            a.z += fmaxf(f1.x, 0.f);
            a.w += fmaxf(f1.y, 0.f);
        }
    }
    *((float4*)(g_h + (size_t)row * DD) + lane) = a;
}

// ---------------- tensor-core GEMM via mma.sync bf16 split (3 passes) --------
// 128-row tiles, 313 blocks, 1 block/SM (proven config).
// MODE0: A=g_h, W1 -> g_h1, fused BN column stats (zero-padded rows add 0).
// MODE1: A=BNrelu(g_h1), W2, +b2 -> out.
#define IMG_BYTES 34816
#define ROW_U32   68
#define SB_IMG    1536
#define GEMM_SMEM (SB_IMG + 4 * IMG_BYTES)

__device__ __forceinline__ void mma_bf16(float* d, uint32_t a0, uint32_t a1,
                                         uint32_t a2, uint32_t a3,
                                         uint32_t b0, uint32_t b1) {
    asm volatile(
        "mma.sync.aligned.m16n8k16.row.col.f32.bf16.bf16.f32 "
        "{%0,%1,%2,%3}, {%4,%5,%6,%7}, {%8,%9}, {%0,%1,%2,%3};"
        : "+f"(d[0]), "+f"(d[1]), "+f"(d[2]), "+f"(d[3])
        : "r"(a0), "r"(a1), "r"(a2), "r"(a3), "r"(b0), "r"(b1));
}

template <int MODE>
__global__ __launch_bounds__(256, 1)
void gemm_tc_kernel(const float* __restrict__ bias2,
                    float* __restrict__ out) {
    extern __shared__ char smem[];
    uint32_t* sAhi = (uint32_t*)(smem + SB_IMG);
    uint32_t* sAlo = (uint32_t*)(smem + SB_IMG + IMG_BYTES);
    uint32_t* sWhi = (uint32_t*)(smem + SB_IMG + 2 * IMG_BYTES);
    uint32_t* sWlo = (uint32_t*)(smem + SB_IMG + 3 * IMG_BYTES);
    float* sF0 = (float*)(smem);          // MODE1: scale | MODE0: col sums
    float* sF1 = (float*)(smem + 512);    // MODE1: shift | MODE0: col sumsq
    float* sB2 = (float*)(smem + 1024);

    int tid  = threadIdx.x;
    int wid  = tid >> 5;
    int lane = tid & 31;
    int r0   = blockIdx.x * 128;

    if (MODE == 1) {
        if (tid < DD) {
            sF0[tid] = g_scale[tid];
            sF1[tid] = g_shift[tid];
            sB2[tid] = bias2[tid];
        }
        __syncthreads();
    } else {
        if (tid < DD) { sF0[tid] = 0.f; sF1[tid] = 0.f; }
    }

    // copy W images (hi+lo = 8192 uint2 total) into padded smem rows
    {
        const uint2* wsrc = (MODE == 0) ? (const uint2*)g_w1img : (const uint2*)g_w2img;
        #pragma unroll
        for (int it = 0; it < 32; ++it) {
            int i = it * 256 + tid;              // 0..8191 uint2
            int half = i >> 12;
            int j = i & 4095;
            int row = j >> 5, c2 = j & 31;
            uint2 v = wsrc[i];
            uint32_t* dst = half ? sWlo : sWhi;
            *reinterpret_cast<uint2*>(dst + row * ROW_U32 + c2 * 2) = v;
        }
    }

    // load + (BN-relu) + split A tile: 128 rows x 128 floats
    {
        const float* A = (MODE == 0) ? g_h : g_h1;
        #pragma unroll
        for (int it = 0; it < 16; ++it) {
            int i   = it * 256 + tid;            // 0..4095 float4
            int row = i >> 5, q = i & 31;
            int gr  = r0 + row;
            int k   = q * 4;
            float4 v;
            if (gr < NN) v = *(const float4*)(A + (size_t)gr * DD + k);
            else         v = make_float4(0.f, 0.f, 0.f, 0.f);
            if (MODE == 1) {
                v.x = fmaxf(fmaf(v.x, sF0[k + 0], sF1[k + 0]), 0.f);
                v.y = fmaxf(fmaf(v.y, sF0[k + 1], sF1[k + 1]), 0.f);
                v.z = fmaxf(fmaf(v.z, sF0[k + 2], sF1[k + 2]), 0.f);
                v.w = fmaxf(fmaf(v.w, sF0[k + 3], sF1[k + 3]), 0.f);
            }
            uint32_t h01 = bf2_bits(v.x, v.y);
            uint32_t h23 = bf2_bits(v.z, v.w);
            __nv_bfloat162* hp01 = reinterpret_cast<__nv_bfloat162*>(&h01);
            __nv_bfloat162* hp23 = reinterpret_cast<__nv_bfloat162*>(&h23);
            float l0 = v.x - __bfloat162float(hp01->x);
            float l1 = v.y - __bfloat162float(hp01->y);
            float l2 = v.z - __bfloat162float(hp23->x);
            float l3 = v.w - __bfloat162float(hp23->y);
            *reinterpret_cast<uint2*>(sAhi + row * ROW_U32 + q * 2) = make_uint2(h01, h23);
            *reinterpret_cast<uint2*>(sAlo + row * ROW_U32 + q * 2) =
                make_uint2(bf2_bits(l0, l1), bf2_bits(l2, l3));
        }
    }
    __syncthreads();

    // warp tiles: warp_m = wid&3 (32 rows -> 2 m16), warp_n = wid>>2 (64 cols -> 8 n8)
    int warp_m = wid & 3;
    int warp_n = wid >> 2;
    int lq = lane >> 2;          // 0..7
    int l4 = lane & 3;           // 0..3
    int mrow0 = warp_m * 32;
    int ncol0 = warp_n * 64;

    float acc[2][8][4];
    #pragma unroll
    for (int mt = 0; mt < 2; ++mt)
        #pragma unroll
        for (int nt = 0; nt < 8; ++nt)
            #pragma unroll
            for (int j = 0; j < 4; ++j) acc[mt][nt][j] = 0.f;

    #pragma unroll
    for (int pass = 0; pass < 3; ++pass) {
        const uint32_t* Ai = (pass == 2) ? sAlo : sAhi;
        const uint32_t* Wi = (pass == 1) ? sWlo : sWhi;
        #pragma unroll
        for (int kt = 0; kt < 8; ++kt) {
            int kc = kt * 8 + l4;                 // u32 column (= bf16 pair index)
            uint32_t a[2][4];
            #pragma unroll
            for (int mt = 0; mt < 2; ++mt) {
                int rb = (mrow0 + mt * 16 + lq) * ROW_U32;
                a[mt][0] = Ai[rb + kc];
                a[mt][1] = Ai[rb + 8 * ROW_U32 + kc];
                a[mt][2] = Ai[rb + kc + 4];
                a[mt][3] = Ai[rb + 8 * ROW_U32 + kc + 4];
            }
            #pragma unroll
            for (int nt = 0; nt < 8; ++nt) {
                int nb = (ncol0 + nt * 8 + lq) * ROW_U32;
                uint32_t b0 = Wi[nb + kc];
                uint32_t b1 = Wi[nb + kc + 4];
                mma_bf16(acc[0][nt], a[0][0], a[0][1], a[0][2], a[0][3], b0, b1);
                mma_bf16(acc[1][nt], a[1][0], a[1][1], a[1][2], a[1][3], b0, b1);
            }
        }
    }

    // epilogue
    #pragma unroll
    for (int mt = 0; mt < 2; ++mt) {
        #pragma unroll
        for (int half = 0; half < 2; ++half) {
            int r = r0 + mrow0 + mt * 16 + half * 8 + lq;
            if (r < NN) {
                #pragma unroll
                for (int nt = 0; nt < 8; ++nt) {
                    int c = ncol0 + nt * 8 + l4 * 2;
                    float2 f;
                    f.x = acc[mt][nt][half * 2 + 0];
                    f.y = acc[mt][nt][half * 2 + 1];
                    if (MODE == 1) {
                        f.x += sB2[c];
                        f.y += sB2[c + 1];
                        *(float2*)(out + (size_t)r * DD + c) = f;
                    } else {
                        *(float2*)(g_h1 + (size_t)r * DD + c) = f;
                    }
                }
            }
        }
    }

    // fused BN stats (MODE 0): zero-padded tail rows contribute exactly 0
    if (MODE == 0) {
        #pragma unroll
        for (int nt = 0; nt < 8; ++nt) {
            int c = ncol0 + nt * 8 + l4 * 2;
            float s0 = 0.f, s1 = 0.f, q0 = 0.f, q1 = 0.f;
            #pragma unroll
            for (int mt = 0; mt < 2; ++mt)
                #pragma unroll
                for (int half = 0; half < 2; ++half) {
                    float vx = acc[mt][nt][half * 2 + 0];
                    float vy = acc[mt][nt][half * 2 + 1];
                    s0 += vx; q0 += vx * vx;
                    s1 += vy; q1 += vy * vy;
                }
            atomicAdd(&sF0[c],     s0);
            atomicAdd(&sF1[c],     q0);
            atomicAdd(&sF0[c + 1], s1);
            atomicAdd(&sF1[c + 1], q1);
        }
        __syncthreads();
        if (tid < DD) {
            atomicAdd(&g_colsum[tid], sF0[tid]);
            atomicAdd(&g_colsq [tid], sF1[tid]);
        }
    }
}

// ---------------- finalize BN scale/shift (+ reset stats accumulators) ------
__global__ void finalize_kernel(const float* __restrict__ gamma,
                                const float* __restrict__ beta) {
    int c = threadIdx.x;
    if (c < DD) {
        float invn = 1.0f / (float)NN;
        float mu  = g_colsum[c] * invn;
        float var = g_colsq[c] * invn - mu * mu;
        float sc  = gamma[c] * rsqrtf(var + 1e-5f);
        g_scale[c] = sc;
        g_shift[c] = beta[c] - mu * sc;
        g_colsum[c] = 0.f;    // restore invariant for next call
        g_colsq [c] = 0.f;
    }
}

// ---------------- launch ----------------
extern "C" void kernel_launch(void* const* d_in, const int* in_sizes, int n_in,
                              void* d_out, int out_size) {
    const float* x     = (const float*)d_in[0];
    const int*   src   = (const int*)  d_in[1];
    const int*   dst   = (const int*)  d_in[2];
    const float* W1    = (const float*)d_in[3];
    const float* gamma = (const float*)d_in[5];
    const float* beta  = (const float*)d_in[6];
    const float* W2    = (const float*)d_in[7];
    const float* b2    = (const float*)d_in[8];
    const float* eps   = (const float*)d_in[9];
    float*       out   = (float*)d_out;

    (void)in_sizes; (void)n_in; (void)out_size;

    cudaFuncSetAttribute(gemm_tc_kernel<0>,
                         cudaFuncAttributeMaxDynamicSharedMemorySize, GEMM_SMEM);
    cudaFuncSetAttribute(gemm_tc_kernel<1>,
                         cudaFuncAttributeMaxDynamicSharedMemorySize, GEMM_SMEM);

    prep_kernel       <<<NN * 32 / 256, 256>>>(x, W1, W2, dst);  // 5000 blocks
    scan_reduce_kernel<<<SCAN_BLKS, 256>>>();
    scan_final_kernel <<<SCAN_BLKS, 256>>>();
    scatter_kernel    <<<EE / 4 / 256, 256>>>(src, dst);
    agg_kernel        <<<NN * 32 / 256, 256>>>(x, eps);

    int gblocks = (NN + 127) / 128;   // 313
    gemm_tc_kernel<0><<<gblocks, 256, GEMM_SMEM>>>(nullptr, nullptr);
    finalize_kernel<<<1, 128>>>(gamma, beta);
    gemm_tc_kernel<1><<<gblocks, 256, GEMM_SMEM>>>(b2, out);
}

// round 14
// speedup vs baseline: 1.3634x; 1.3634x over previous
#include <cuda_runtime.h>
#include <cuda_bf16.h>
#include <cuda_fp16.h>
#include <cstdint>

#define NN 40000
#define DD 128
#define EE 640000
#define SCAN_BLKS ((NN + 255) / 256)   // 157

// ---------------- device scratch (static, no allocation) ----------------
__device__ float    g_h  [(size_t)NN * DD];  // h = (1+eps)*x + agg
__device__ float    g_h1 [(size_t)NN * DD];  // h @ W1.T (b1 dropped: BN shift-invariant)
__device__ uint32_t g_xh [(size_t)NN * 64];  // fp16 copy of x (half2-packed)
__device__ int      g_csr[EE];
__device__ int      g_cnt[NN];
__device__ int      g_off[NN + 1];
__device__ int      g_cur[NN];
__device__ int      g_bsum[SCAN_BLKS];
__device__ float    g_colsum[DD];
__device__ float    g_colsq [DD];
__device__ float    g_scale [DD];
__device__ float    g_shift [DD];
// flat bf16 images per W: hi = u32[0:8192), lo = u32[8192:16384)  ([row][64] u32)
__device__ uint32_t g_w1img[16384];
__device__ uint32_t g_w2img[16384];

__device__ __forceinline__ uint32_t bf2_bits(float a, float b) {
    __nv_bfloat162 t = __floats2bfloat162_rn(a, b);
    return *reinterpret_cast<uint32_t*>(&t);
}
__device__ __forceinline__ uint32_t h2_bits(float a, float b) {
    __half2 t = __floats2half2_rn(a, b);
    return *reinterpret_cast<uint32_t*>(&t);
}

// ---------------- prep: zero counters/stats + W split + x->fp16 ----------------
__global__ __launch_bounds__(256)
void prep_kernel(const float* __restrict__ x,
                 const float* __restrict__ W1,
                 const float* __restrict__ W2) {
    int i = blockIdx.x * 256 + threadIdx.x;

    // x -> fp16 (NN*32 float4 quads)
    if (i < NN * 32) {
        int row = i >> 5, q = i & 31;
        float4 v = *(const float4*)(x + (size_t)row * DD + q * 4);
        *reinterpret_cast<uint2*>(g_xh + row * 64 + q * 2) =
            make_uint2(h2_bits(v.x, v.y), h2_bits(v.z, v.w));
    }
    if (i < NN) g_cnt[i] = 0;
    if (i < DD) { g_colsum[i] = 0.f; g_colsq[i] = 0.f; }

    // W split (8192 float4 quads across both W's)
    if (i < 8192) {
        const float* W = (i < 4096) ? W1 : W2;
        uint32_t*  img = (i < 4096) ? g_w1img : g_w2img;
        int j = i & 4095;
        int row = j >> 5, q = j & 31;
        float4 v = *(const float4*)(W + (size_t)row * DD + q * 4);
        uint32_t h01 = bf2_bits(v.x, v.y);
        uint32_t h23 = bf2_bits(v.z, v.w);
        __nv_bfloat162* hp01 = reinterpret_cast<__nv_bfloat162*>(&h01);
        __nv_bfloat162* hp23 = reinterpret_cast<__nv_bfloat162*>(&h23);
        float l0 = v.x - __bfloat162float(hp01->x);
        float l1 = v.y - __bfloat162float(hp01->y);
        float l2 = v.z - __bfloat162float(hp23->x);
        float l3 = v.w - __bfloat162float(hp23->y);
        *reinterpret_cast<uint2*>(img + row * 64 + 2 * q) = make_uint2(h01, h23);
        *reinterpret_cast<uint2*>(img + 8192 + row * 64 + 2 * q) =
            make_uint2(bf2_bits(l0, l1), bf2_bits(l2, l3));
    }
}

// ---------------- K1: histogram of dst (8 edges/thread for MLP) ----------------
__global__ void hist_kernel(const int* __restrict__ dst) {
    int e = (blockIdx.x * blockDim.x + threadIdx.x) * 8;
    if (e < EE) {   // EE % 8 == 0: all covered groups are full
        int4 d0 = *(const int4*)(dst + e);
        int4 d1 = *(const int4*)(dst + e + 4);
        atomicAdd(&g_cnt[d0.x], 1);
        atomicAdd(&g_cnt[d0.y], 1);
        atomicAdd(&g_cnt[d0.z], 1);
        atomicAdd(&g_cnt[d0.w], 1);
        atomicAdd(&g_cnt[d1.x], 1);
        atomicAdd(&g_cnt[d1.y], 1);
        atomicAdd(&g_cnt[d1.z], 1);
        atomicAdd(&g_cnt[d1.w], 1);
    }
}

// ---------------- K2a: per-block reduce of cnt ----------------
__global__ __launch_bounds__(256)
void scan_reduce_kernel() {
    int i = blockIdx.x * 256 + threadIdx.x;
    int v = (i < NN) ? g_cnt[i] : 0;
    #pragma unroll
    for (int o = 16; o > 0; o >>= 1) v += __shfl_down_sync(0xffffffffu, v, o);
    __shared__ int ws[8];
    if ((threadIdx.x & 31) == 0) ws[threadIdx.x >> 5] = v;
    __syncthreads();
    if (threadIdx.x < 8) {
        int s = ws[threadIdx.x];
        #pragma unroll
        for (int o = 4; o > 0; o >>= 1) s += __shfl_down_sync(0xffu, s, o);
        if (threadIdx.x == 0) g_bsum[blockIdx.x] = s;
    }
}

// ---------------- K2b: final scan (each block redundantly scans g_bsum) ----
__global__ __launch_bounds__(256)
void scan_final_kernel() {
    __shared__ int sh[256];
    __shared__ int wtot[8];
    int t = threadIdx.x;

    // redundant in-block scan of the 157 block sums (L2-hot, ~0.3us)
    int bs = (t < SCAN_BLKS) ? g_bsum[t] : 0;
    sh[t] = bs;
    __syncthreads();
    #pragma unroll
    for (int o = 1; o < 256; o <<= 1) {
        int u = (t >= o) ? sh[t - o] : 0;
        __syncthreads();
        sh[t] += u;
        __syncthreads();
    }
    int myboff = (blockIdx.x == 0) ? 0 : sh[blockIdx.x - 1];   // exclusive

    // per-element scan within this block's 256 elements
    int i = blockIdx.x * 256 + t;
    int lane = t & 31, wrp = t >> 5;
    int v = (i < NN) ? g_cnt[i] : 0;
    int inc = v;
    #pragma unroll
    for (int o = 1; o < 32; o <<= 1) {
        int u = __shfl_up_sync(0xffffffffu, inc, o);
        if (lane >= o) inc += u;
    }
    if (lane == 31) wtot[wrp] = inc;
    __syncthreads();
    if (t < 8) {
        int s = wtot[t];
        #pragma unroll
        for (int o = 1; o < 8; o <<= 1) {
            int u = __shfl_up_sync(0xffu, s, o);
            if (t >= o) s += u;
        }
        wtot[t] = s - wtot[t];   // exclusive warp offsets
    }
    __syncthreads();
    int off = myboff + wtot[wrp] + (inc - v);
    if (i < NN) { g_off[i] = off; g_cur[i] = off; }
    if (blockIdx.x == 0 && t == 0) g_off[NN] = EE;
}

// ---------------- K3: scatter edges into CSR (8 edges/thread for MLP) --------
__global__ void scatter_kernel(const int* __restrict__ src,
                               const int* __restrict__ dst) {
    int e = (blockIdx.x * blockDim.x + threadIdx.x) * 8;
    if (e < EE) {
        int4 d0 = *(const int4*)(dst + e);
        int4 d1 = *(const int4*)(dst + e + 4);
        int4 s0 = *(const int4*)(src + e);
        int4 s1 = *(const int4*)(src + e + 4);
        g_csr[atomicAdd(&g_cur[d0.x], 1)] = s0.x;
        g_csr[atomicAdd(&g_cur[d0.y], 1)] = s0.y;
        g_csr[atomicAdd(&g_cur[d0.z], 1)] = s0.z;
        g_csr[atomicAdd(&g_cur[d0.w], 1)] = s0.w;
        g_csr[atomicAdd(&g_cur[d1.x], 1)] = s1.x;
        g_csr[atomicAdd(&g_cur[d1.y], 1)] = s1.y;
        g_csr[atomicAdd(&g_cur[d1.z], 1)] = s1.z;
        g_csr[atomicAdd(&g_cur[d1.w], 1)] = s1.w;
    }
}

// ---------------- K4: aggregate (one warp per row, fp16 gather) ----------------
__global__ __launch_bounds__(256)
void agg_kernel(const float* __restrict__ x, const float* __restrict__ eps) {
    int gt   = blockIdx.x * blockDim.x + threadIdx.x;
    int row  = gt >> 5;
    int lane = gt & 31;
    if (row >= NN) return;

    float s0 = 1.0f + eps[0];
    float4 a = *((const float4*)(x + (size_t)row * DD) + lane);
    a.x *= s0; a.y *= s0; a.z *= s0; a.w *= s0;

    int jb = g_off[row], je = g_off[row + 1];
    for (int j0 = jb; j0 < je; j0 += 32) {
        int rem = je - j0;
        int myidx = (lane < rem) ? g_csr[j0 + lane] : 0;
        int cnt = rem < 32 ? rem : 32;
        for (int t = 0; t < cnt; ++t) {
            int sidx = __shfl_sync(0xffffffffu, myidx, t);
            uint2 hv = *((const uint2*)(g_xh + (size_t)sidx * 64) + lane);
            float2 f0 = __half22float2(*reinterpret_cast<__half2*>(&hv.x));
            float2 f1 = __half22float2(*reinterpret_cast<__half2*>(&hv.y));
            a.x += fmaxf(f0.x, 0.f);
            a.y += fmaxf(f0.y, 0.f);
            a.z += fmaxf(f1.x, 0.f);
            a.w += fmaxf(f1.y, 0.f);
        }
    }
    *((float4*)(g_h + (size_t)row * DD) + lane) = a;
}

// ---------------- tensor-core GEMM via mma.sync bf16 split (3 passes) --------
// 128-row tiles, 313 blocks, 1 block/SM (proven config).
#define IMG_BYTES 34816
#define ROW_U32   68
#define SB_IMG    1536
#define GEMM_SMEM (SB_IMG + 4 * IMG_BYTES)

__device__ __forceinline__ void mma_bf16(float* d, uint32_t a0, uint32_t a1,
                                         uint32_t a2, uint32_t a3,
                                         uint32_t b0, uint32_t b1) {
    asm volatile(
        "mma.sync.aligned.m16n8k16.row.col.f32.bf16.bf16.f32 "
        "{%0,%1,%2,%3}, {%4,%5,%6,%7}, {%8,%9}, {%0,%1,%2,%3};"
        : "+f"(d[0]), "+f"(d[1]), "+f"(d[2]), "+f"(d[3])
        : "r"(a0), "r"(a1), "r"(a2), "r"(a3), "r"(b0), "r"(b1));
}

template <int MODE>
__global__ __launch_bounds__(256, 1)
void gemm_tc_kernel(const float* __restrict__ bias2,
                    float* __restrict__ out) {
    extern __shared__ char smem[];
    uint32_t* sAhi = (uint32_t*)(smem + SB_IMG);
    uint32_t* sAlo = (uint32_t*)(smem + SB_IMG + IMG_BYTES);
    uint32_t* sWhi = (uint32_t*)(smem + SB_IMG + 2 * IMG_BYTES);
    uint32_t* sWlo = (uint32_t*)(smem + SB_IMG + 3 * IMG_BYTES);
    float* sScale = (float*)(smem);
    float* sShift = (float*)(smem + 512);
    float* sB2    = (float*)(smem + 1024);

    int tid  = threadIdx.x;
    int wid  = tid >> 5;
    int lane = tid & 31;
    int r0   = blockIdx.x * 128;

    if (MODE == 1 && tid < DD) {
        sScale[tid] = g_scale[tid];
        sShift[tid] = g_shift[tid];
        sB2[tid]    = bias2[tid];
    }
    if (MODE == 1) __syncthreads();

    // copy W images (hi+lo = 8192 uint2 total) into padded smem rows
    {
        const uint2* wsrc = (MODE == 0) ? (const uint2*)g_w1img : (const uint2*)g_w2img;
        #pragma unroll
        for (int it = 0; it < 32; ++it) {
            int i = it * 256 + tid;              // 0..8191 uint2
            int half = i >> 12;
            int j = i & 4095;
            int row = j >> 5, c2 = j & 31;
            uint2 v = wsrc[i];
            uint32_t* dst = half ? sWlo : sWhi;
            *reinterpret_cast<uint2*>(dst + row * ROW_U32 + c2 * 2) = v;
        }
    }

    // load + (BN-relu) + split A tile: 128 rows x 128 floats
    {
        const float* A = (MODE == 0) ? g_h : g_h1;
        #pragma unroll
        for (int it = 0; it < 16; ++it) {
            int i   = it * 256 + tid;            // 0..4095 float4
            int row = i >> 5, q = i & 31;
            int gr  = r0 + row;
            int k   = q * 4;
            float4 v;
            if (gr < NN) v = *(const float4*)(A + (size_t)gr * DD + k);
            else         v = make_float4(0.f, 0.f, 0.f, 0.f);
            if (MODE == 1) {
                v.x = fmaxf(fmaf(v.x, sScale[k + 0], sShift[k + 0]), 0.f);
                v.y = fmaxf(fmaf(v.y, sScale[k + 1], sShift[k + 1]), 0.f);
                v.z = fmaxf(fmaf(v.z, sScale[k + 2], sShift[k + 2]), 0.f);
                v.w = fmaxf(fmaf(v.w, sScale[k + 3], sShift[k + 3]), 0.f);
            }
            uint32_t h01 = bf2_bits(v.x, v.y);
            uint32_t h23 = bf2_bits(v.z, v.w);
            __nv_bfloat162* hp01 = reinterpret_cast<__nv_bfloat162*>(&h01);
            __nv_bfloat162* hp23 = reinterpret_cast<__nv_bfloat162*>(&h23);
            float l0 = v.x - __bfloat162float(hp01->x);
            float l1 = v.y - __bfloat162float(hp01->y);
            float l2 = v.z - __bfloat162float(hp23->x);
            float l3 = v.w - __bfloat162float(hp23->y);
            *reinterpret_cast<uint2*>(sAhi + row * ROW_U32 + q * 2) = make_uint2(h01, h23);
            *reinterpret_cast<uint2*>(sAlo + row * ROW_U32 + q * 2) =
                make_uint2(bf2_bits(l0, l1), bf2_bits(l2, l3));
        }
    }
    __syncthreads();

    // warp tiles: warp_m = wid&3 (32 rows -> 2 m16), warp_n = wid>>2 (64 cols -> 8 n8)
    int warp_m = wid & 3;
    int warp_n = wid >> 2;
    int lq = lane >> 2;          // 0..7
    int l4 = lane & 3;           // 0..3
    int mrow0 = warp_m * 32;
    int ncol0 = warp_n * 64;

    float acc[2][8][4];
    #pragma unroll
    for (int mt = 0; mt < 2; ++mt)
        #pragma unroll
        for (int nt = 0; nt < 8; ++nt)
            #pragma unroll
            for (int j = 0; j < 4; ++j) acc[mt][nt][j] = 0.f;

    #pragma unroll
    for (int pass = 0; pass < 3; ++pass) {
        const uint32_t* Ai = (pass == 2) ? sAlo : sAhi;
        const uint32_t* Wi = (pass == 1) ? sWlo : sWhi;
        #pragma unroll
        for (int kt = 0; kt < 8; ++kt) {
            int kc = kt * 8 + l4;                 // u32 column (= bf16 pair index)
            uint32_t a[2][4];
            #pragma unroll
            for (int mt = 0; mt < 2; ++mt) {
                int rb = (mrow0 + mt * 16 + lq) * ROW_U32;
                a[mt][0] = Ai[rb + kc];
                a[mt][1] = Ai[rb + 8 * ROW_U32 + kc];
                a[mt][2] = Ai[rb + kc + 4];
                a[mt][3] = Ai[rb + 8 * ROW_U32 + kc + 4];
            }
            #pragma unroll
            for (int nt = 0; nt < 8; ++nt) {
                int nb = (ncol0 + nt * 8 + lq) * ROW_U32;
                uint32_t b0 = Wi[nb + kc];
                uint32_t b1 = Wi[nb + kc + 4];
                mma_bf16(acc[0][nt], a[0][0], a[0][1], a[0][2], a[0][3], b0, b1);
                mma_bf16(acc[1][nt], a[1][0], a[1][1], a[1][2], a[1][3], b0, b1);
            }
        }
    }

    // epilogue
    #pragma unroll
    for (int mt = 0; mt < 2; ++mt) {
        #pragma unroll
        for (int half = 0; half < 2; ++half) {
            int r = r0 + mrow0 + mt * 16 + half * 8 + lq;
            if (r < NN) {
                #pragma unroll
                for (int nt = 0; nt < 8; ++nt) {
                    int c = ncol0 + nt * 8 + l4 * 2;
                    float2 f;
                    f.x = acc[mt][nt][half * 2 + 0];
                    f.y = acc[mt][nt][half * 2 + 1];
                    if (MODE == 1) {
                        f.x += sB2[c];
                        f.y += sB2[c + 1];
                        *(float2*)(out + (size_t)r * DD + c) = f;
                    } else {
                        *(float2*)(g_h1 + (size_t)r * DD + c) = f;
                    }
                }
            }
        }
    }
}

// ---------------- BN column stats over g_h1 ----------------
__global__ __launch_bounds__(256)
void stats_kernel() {
    int tid = threadIdx.x;
    int q = tid & 31;      // col quad
    int rt = tid >> 5;     // 0..7
    float4 s  = make_float4(0.f, 0.f, 0.f, 0.f);
    float4 sq = make_float4(0.f, 0.f, 0.f, 0.f);
    for (int r = blockIdx.x * 8 + rt; r < NN; r += 8 * 160) {
        float4 v = *(const float4*)(g_h1 + (size_t)r * DD + q * 4);
        s.x += v.x; s.y += v.y; s.z += v.z; s.w += v.w;
        sq.x += v.x * v.x; sq.y += v.y * v.y;
        sq.z += v.z * v.z; sq.w += v.w * v.w;
    }
    __shared__ float4 ss[8][32], qq[8][32];
    ss[rt][q] = s; qq[rt][q] = sq;
    __syncthreads();
    if (rt == 0) {
        #pragma unroll
        for (int i = 1; i < 8; ++i) {
            s.x += ss[i][q].x; s.y += ss[i][q].y; s.z += ss[i][q].z; s.w += ss[i][q].w;
            sq.x += qq[i][q].x; sq.y += qq[i][q].y; sq.z += qq[i][q].z; sq.w += qq[i][q].w;
        }
        atomicAdd(&g_colsum[q * 4 + 0], s.x);
        atomicAdd(&g_colsum[q * 4 + 1], s.y);
        atomicAdd(&g_colsum[q * 4 + 2], s.z);
        atomicAdd(&g_colsum[q * 4 + 3], s.w);
        atomicAdd(&g_colsq[q * 4 + 0], sq.x);
        atomicAdd(&g_colsq[q * 4 + 1], sq.y);
        atomicAdd(&g_colsq[q * 4 + 2], sq.z);
        atomicAdd(&g_colsq[q * 4 + 3], sq.w);
    }
}

// ---------------- finalize BN scale/shift ----------------
__global__ void finalize_kernel(const float* __restrict__ gamma,
                                const float* __restrict__ beta) {
    int c = threadIdx.x;
    if (c < DD) {
        float invn = 1.0f / (float)NN;
        float mu  = g_colsum[c] * invn;
        float var = g_colsq[c] * invn - mu * mu;
        float sc  = gamma[c] * rsqrtf(var + 1e-5f);
        g_scale[c] = sc;
        g_shift[c] = beta[c] - mu * sc;
    }
}

// ---------------- launch ----------------
extern "C" void kernel_launch(void* const* d_in, const int* in_sizes, int n_in,
                              void* d_out, int out_size) {
    const float* x     = (const float*)d_in[0];
    const int*   src   = (const int*)  d_in[1];
    const int*   dst   = (const int*)  d_in[2];
    const float* W1    = (const float*)d_in[3];
    const float* gamma = (const float*)d_in[5];
    const float* beta  = (const float*)d_in[6];
    const float* W2    = (const float*)d_in[7];
    const float* b2    = (const float*)d_in[8];
    const float* eps   = (const float*)d_in[9];
    float*       out   = (float*)d_out;

    (void)in_sizes; (void)n_in; (void)out_size;

    cudaFuncSetAttribute(gemm_tc_kernel<0>,
                         cudaFuncAttributeMaxDynamicSharedMemorySize, GEMM_SMEM);
    cudaFuncSetAttribute(gemm_tc_kernel<1>,
                         cudaFuncAttributeMaxDynamicSharedMemorySize, GEMM_SMEM);

    prep_kernel       <<<NN * 32 / 256, 256>>>(x, W1, W2);   // 5000 blocks
    hist_kernel       <<<(EE / 8 + 255) / 256, 256>>>(dst);  // 313 blocks
    scan_reduce_kernel<<<SCAN_BLKS, 256>>>();
    scan_final_kernel <<<SCAN_BLKS, 256>>>();
    scatter_kernel    <<<(EE / 8 + 255) / 256, 256>>>(src, dst);
    agg_kernel        <<<NN * 32 / 256, 256>>>(x, eps);

    int gblocks = (NN + 127) / 128;   // 313
    gemm_tc_kernel<0><<<gblocks, 256, GEMM_SMEM>>>(nullptr, nullptr);
    stats_kernel   <<<160, 256>>>();
    finalize_kernel<<<1, 128>>>(gamma, beta);
    gemm_tc_kernel<1><<<gblocks, 256, GEMM_SMEM>>>(b2, out);
}

// round 15
// speedup vs baseline: 1.3773x; 1.0101x over previous
#include <cuda_runtime.h>
#include <cuda_bf16.h>
#include <cuda_fp16.h>
#include <cstdint>

#define NN 40000
#define DD 128
#define EE 640000
#define SCAN_BLKS ((NN + 255) / 256)   // 157
#define READY (1 << 30)

// ---------------- device scratch (static, no allocation) ----------------
__device__ float    g_h  [(size_t)NN * DD];  // h = (1+eps)*x + agg
__device__ float    g_h1 [(size_t)NN * DD];  // h @ W1.T (b1 dropped: BN shift-invariant)
__device__ uint32_t g_xh [(size_t)NN * 64];  // fp16 copy of x (half2-packed)
__device__ int      g_csr[EE];
__device__ int      g_cnt[NN];
__device__ int      g_off[NN + 1];
__device__ int      g_cur[NN];
__device__ int      g_bsum[SCAN_BLKS];
__device__ float    g_colsum[DD];
__device__ float    g_colsq [DD];
// flat bf16 images per W: hi = u32[0:8192), lo = u32[8192:16384)  ([row][64] u32)
__device__ uint32_t g_w1img[16384];
__device__ uint32_t g_w2img[16384];

__device__ __forceinline__ uint32_t bf2_bits(float a, float b) {
    __nv_bfloat162 t = __floats2bfloat162_rn(a, b);
    return *reinterpret_cast<uint32_t*>(&t);
}
__device__ __forceinline__ uint32_t h2_bits(float a, float b) {
    __half2 t = __floats2half2_rn(a, b);
    return *reinterpret_cast<uint32_t*>(&t);
}

// ---------------- prep: zero counters/stats + W split + x->fp16 ----------------
__global__ __launch_bounds__(256)
void prep_kernel(const float* __restrict__ x,
                 const float* __restrict__ W1,
                 const float* __restrict__ W2) {
    int i = blockIdx.x * 256 + threadIdx.x;

    // x -> fp16 (NN*32 float4 quads)
    if (i < NN * 32) {
        int row = i >> 5, q = i & 31;
        float4 v = *(const float4*)(x + (size_t)row * DD + q * 4);
        *reinterpret_cast<uint2*>(g_xh + row * 64 + q * 2) =
            make_uint2(h2_bits(v.x, v.y), h2_bits(v.z, v.w));
    }
    if (i < NN) g_cnt[i] = 0;
    if (i < SCAN_BLKS) g_bsum[i] = 0;
    if (i < DD) { g_colsum[i] = 0.f; g_colsq[i] = 0.f; }

    // W split (8192 float4 quads across both W's)
    if (i < 8192) {
        const float* W = (i < 4096) ? W1 : W2;
        uint32_t*  img = (i < 4096) ? g_w1img : g_w2img;
        int j = i & 4095;
        int row = j >> 5, q = j & 31;
        float4 v = *(const float4*)(W + (size_t)row * DD + q * 4);
        uint32_t h01 = bf2_bits(v.x, v.y);
        uint32_t h23 = bf2_bits(v.z, v.w);
        __nv_bfloat162* hp01 = reinterpret_cast<__nv_bfloat162*>(&h01);
        __nv_bfloat162* hp23 = reinterpret_cast<__nv_bfloat162*>(&h23);
        float l0 = v.x - __bfloat162float(hp01->x);
        float l1 = v.y - __bfloat162float(hp01->y);
        float l2 = v.z - __bfloat162float(hp23->x);
        float l3 = v.w - __bfloat162float(hp23->y);
        *reinterpret_cast<uint2*>(img + row * 64 + 2 * q) = make_uint2(h01, h23);
        *reinterpret_cast<uint2*>(img + 8192 + row * 64 + 2 * q) =
            make_uint2(bf2_bits(l0, l1), bf2_bits(l2, l3));
    }
}

// ---------------- K1: histogram of dst (8 edges/thread) ----------------
__global__ void hist_kernel(const int* __restrict__ dst) {
    int e = (blockIdx.x * blockDim.x + threadIdx.x) * 8;
    if (e < EE) {   // EE % 8 == 0
        int4 d0 = *(const int4*)(dst + e);
        int4 d1 = *(const int4*)(dst + e + 4);
        atomicAdd(&g_cnt[d0.x], 1);
        atomicAdd(&g_cnt[d0.y], 1);
        atomicAdd(&g_cnt[d0.z], 1);
        atomicAdd(&g_cnt[d0.w], 1);
        atomicAdd(&g_cnt[d1.x], 1);
        atomicAdd(&g_cnt[d1.y], 1);
        atomicAdd(&g_cnt[d1.z], 1);
        atomicAdd(&g_cnt[d1.w], 1);
    }
}

// ---------------- K2: single-pass scan with decoupled lookback ----------------
// All 157 blocks co-resident (tiny footprint) -> no progress hazard.
// Aggregate+flag share one 32-bit word (counts < 2^20), so no fence needed.
__global__ __launch_bounds__(256)
void scan_kernel() {
    __shared__ int wsum[8], woff[9], pw[8], boff;
    int bid = blockIdx.x, t = threadIdx.x;
    int lane = t & 31, wrp = t >> 5;
    int i = bid * 256 + t;
    int v = (i < NN) ? g_cnt[i] : 0;

    // intra-warp inclusive scan
    int inc = v;
    #pragma unroll
    for (int o = 1; o < 32; o <<= 1) {
        int u = __shfl_up_sync(0xffffffffu, inc, o);
        if (lane >= o) inc += u;
    }
    if (lane == 31) wsum[wrp] = inc;
    __syncthreads();
    if (t == 0) {
        int r = 0;
        #pragma unroll
        for (int k = 0; k < 8; ++k) { woff[k] = r; r += wsum[k]; }
        woff[8] = r;
        atomicExch(&g_bsum[bid], r | READY);   // publish aggregate early
    }
    __syncthreads();

    // lookback: poll predecessor aggregates (<= 1 slot per thread)
    int pre = 0;
    for (int s = t; s < bid; s += 256) {
        int val;
        do { val = atomicAdd(&g_bsum[s], 0); } while (!(val & READY));
        pre += val & (READY - 1);
    }
    #pragma unroll
    for (int o = 16; o > 0; o >>= 1) pre += __shfl_down_sync(0xffffffffu, pre, o);
    if (lane == 0) pw[wrp] = pre;
    __syncthreads();
    if (t == 0) {
        int r = 0;
        #pragma unroll
        for (int k = 0; k < 8; ++k) r += pw[k];
        boff = r;
    }
    __syncthreads();

    int off = boff + woff[wrp] + (inc - v);
    if (i < NN) { g_off[i] = off; g_cur[i] = off; }
    if (bid == 0 && t == 0) g_off[NN] = EE;
}

// ---------------- K3: scatter edges into CSR (8 edges/thread) ----------------
__global__ void scatter_kernel(const int* __restrict__ src,
                               const int* __restrict__ dst) {
    int e = (blockIdx.x * blockDim.x + threadIdx.x) * 8;
    if (e < EE) {
        int4 d0 = *(const int4*)(dst + e);
        int4 d1 = *(const int4*)(dst + e + 4);
        int4 s0 = *(const int4*)(src + e);
        int4 s1 = *(const int4*)(src + e + 4);
        g_csr[atomicAdd(&g_cur[d0.x], 1)] = s0.x;
        g_csr[atomicAdd(&g_cur[d0.y], 1)] = s0.y;
        g_csr[atomicAdd(&g_cur[d0.z], 1)] = s0.z;
        g_csr[atomicAdd(&g_cur[d0.w], 1)] = s0.w;
        g_csr[atomicAdd(&g_cur[d1.x], 1)] = s1.x;
        g_csr[atomicAdd(&g_cur[d1.y], 1)] = s1.y;
        g_csr[atomicAdd(&g_cur[d1.z], 1)] = s1.z;
        g_csr[atomicAdd(&g_cur[d1.w], 1)] = s1.w;
    }
}

// ---------------- K4: aggregate (one warp per row, fp16 gather, 4-wide MLP) ----
__global__ __launch_bounds__(256)
void agg_kernel(const float* __restrict__ x, const float* __restrict__ eps) {
    int gt   = blockIdx.x * blockDim.x + threadIdx.x;
    int row  = gt >> 5;
    int lane = gt & 31;
    if (row >= NN) return;

    float s0 = 1.0f + eps[0];
    float4 a = *((const float4*)(x + (size_t)row * DD) + lane);
    a.x *= s0; a.y *= s0; a.z *= s0; a.w *= s0;

    int jb = g_off[row], je = g_off[row + 1];
    for (int j0 = jb; j0 < je; j0 += 32) {
        int rem = je - j0;
        int cnt = rem < 32 ? rem : 32;
        int myidx = (lane < cnt) ? g_csr[j0 + lane] : 0;
        int t = 0;
        // 4-wide: 4 independent gathers in flight per iteration
        for (; t + 4 <= cnt; t += 4) {
            int i0 = __shfl_sync(0xffffffffu, myidx, t);
            int i1 = __shfl_sync(0xffffffffu, myidx, t + 1);
            int i2 = __shfl_sync(0xffffffffu, myidx, t + 2);
            int i3 = __shfl_sync(0xffffffffu, myidx, t + 3);
            uint2 h0 = *((const uint2*)(g_xh + (size_t)i0 * 64) + lane);
            uint2 h1 = *((const uint2*)(g_xh + (size_t)i1 * 64) + lane);
            uint2 h2 = *((const uint2*)(g_xh + (size_t)i2 * 64) + lane);
            uint2 h3 = *((const uint2*)(g_xh + (size_t)i3 * 64) + lane);
            float2 a0 = __half22float2(*reinterpret_cast<__half2*>(&h0.x));
            float2 b0 = __half22float2(*reinterpret_cast<__half2*>(&h0.y));
            float2 a1 = __half22float2(*reinterpret_cast<__half2*>(&h1.x));
            float2 b1 = __half22float2(*reinterpret_cast<__half2*>(&h1.y));
            float2 a2 = __half22float2(*reinterpret_cast<__half2*>(&h2.x));
            float2 b2 = __half22float2(*reinterpret_cast<__half2*>(&h2.y));
            float2 a3 = __half22float2(*reinterpret_cast<__half2*>(&h3.x));
            float2 b3 = __half22float2(*reinterpret_cast<__half2*>(&h3.y));
            a.x += fmaxf(a0.x, 0.f) + fmaxf(a1.x, 0.f) + fmaxf(a2.x, 0.f) + fmaxf(a3.x, 0.f);
            a.y += fmaxf(a0.y, 0.f) + fmaxf(a1.y, 0.f) + fmaxf(a2.y, 0.f) + fmaxf(a3.y, 0.f);
            a.z += fmaxf(b0.x, 0.f) + fmaxf(b1.x, 0.f) + fmaxf(b2.x, 0.f) + fmaxf(b3.x, 0.f);
            a.w += fmaxf(b0.y, 0.f) + fmaxf(b1.y, 0.f) + fmaxf(b2.y, 0.f) + fmaxf(b3.y, 0.f);
        }
        for (; t < cnt; ++t) {
            int sidx = __shfl_sync(0xffffffffu, myidx, t);
            uint2 hv = *((const uint2*)(g_xh + (size_t)sidx * 64) + lane);
            float2 f0 = __half22float2(*reinterpret_cast<__half2*>(&hv.x));
            float2 f1 = __half22float2(*reinterpret_cast<__half2*>(&hv.y));
            a.x += fmaxf(f0.x, 0.f);
            a.y += fmaxf(f0.y, 0.f);
            a.z += fmaxf(f1.x, 0.f);
            a.w += fmaxf(f1.y, 0.f);
        }
    }
    *((float4*)(g_h + (size_t)row * DD) + lane) = a;
}

// ---------------- tensor-core GEMM via mma.sync bf16 split (3 passes) --------
// 128-row tiles, 313 blocks, 1 block/SM (proven config).
// MODE1 computes BN scale/shift per block from g_colsum/g_colsq (read-only).
#define IMG_BYTES 34816
#define ROW_U32   68
#define SB_IMG    1536
#define GEMM_SMEM (SB_IMG + 4 * IMG_BYTES)

__device__ __forceinline__ void mma_bf16(float* d, uint32_t a0, uint32_t a1,
                                         uint32_t a2, uint32_t a3,
                                         uint32_t b0, uint32_t b1) {
    asm volatile(
        "mma.sync.aligned.m16n8k16.row.col.f32.bf16.bf16.f32 "
        "{%0,%1,%2,%3}, {%4,%5,%6,%7}, {%8,%9}, {%0,%1,%2,%3};"
        : "+f"(d[0]), "+f"(d[1]), "+f"(d[2]), "+f"(d[3])
        : "r"(a0), "r"(a1), "r"(a2), "r"(a3), "r"(b0), "r"(b1));
}

template <int MODE>
__global__ __launch_bounds__(256, 1)
void gemm_tc_kernel(const float* __restrict__ gamma,
                    const float* __restrict__ beta,
                    const float* __restrict__ bias2,
                    float* __restrict__ out) {
    extern __shared__ char smem[];
    uint32_t* sAhi = (uint32_t*)(smem + SB_IMG);
    uint32_t* sAlo = (uint32_t*)(smem + SB_IMG + IMG_BYTES);
    uint32_t* sWhi = (uint32_t*)(smem + SB_IMG + 2 * IMG_BYTES);
    uint32_t* sWlo = (uint32_t*)(smem + SB_IMG + 3 * IMG_BYTES);
    float* sScale = (float*)(smem);
    float* sShift = (float*)(smem + 512);
    float* sB2    = (float*)(smem + 1024);

    int tid  = threadIdx.x;
    int wid  = tid >> 5;
    int lane = tid & 31;
    int r0   = blockIdx.x * 128;

    if (MODE == 1) {
        if (tid < DD) {
            // per-block BN finalize (redundant, read-only, L2-hot)
            float invn = 1.0f / (float)NN;
            float mu  = g_colsum[tid] * invn;
            float var = g_colsq[tid] * invn - mu * mu;
            float sc  = gamma[tid] * rsqrtf(var + 1e-5f);
            sScale[tid] = sc;
            sShift[tid] = beta[tid] - mu * sc;
            sB2[tid]    = bias2[tid];
        }
        __syncthreads();
    }

    // copy W images (hi+lo = 8192 uint2 total) into padded smem rows
    {
        const uint2* wsrc = (MODE == 0) ? (const uint2*)g_w1img : (const uint2*)g_w2img;
        #pragma unroll
        for (int it = 0; it < 32; ++it) {
            int i = it * 256 + tid;              // 0..8191 uint2
            int half = i >> 12;
            int j = i & 4095;
            int row = j >> 5, c2 = j & 31;
            uint2 v = wsrc[i];
            uint32_t* dst = half ? sWlo : sWhi;
            *reinterpret_cast<uint2*>(dst + row * ROW_U32 + c2 * 2) = v;
        }
    }

    // load + (BN-relu) + split A tile: 128 rows x 128 floats
    {
        const float* A = (MODE == 0) ? g_h : g_h1;
        #pragma unroll
        for (int it = 0; it < 16; ++it) {
            int i   = it * 256 + tid;            // 0..4095 float4
            int row = i >> 5, q = i & 31;
            int gr  = r0 + row;
            int k   = q * 4;
            float4 v;
            if (gr < NN) v = *(const float4*)(A + (size_t)gr * DD + k);
            else         v = make_float4(0.f, 0.f, 0.f, 0.f);
            if (MODE == 1) {
                v.x = fmaxf(fmaf(v.x, sScale[k + 0], sShift[k + 0]), 0.f);
                v.y = fmaxf(fmaf(v.y, sScale[k + 1], sShift[k + 1]), 0.f);
                v.z = fmaxf(fmaf(v.z, sScale[k + 2], sShift[k + 2]), 0.f);
                v.w = fmaxf(fmaf(v.w, sScale[k + 3], sShift[k + 3]), 0.f);
            }
            uint32_t h01 = bf2_bits(v.x, v.y);
            uint32_t h23 = bf2_bits(v.z, v.w);
            __nv_bfloat162* hp01 = reinterpret_cast<__nv_bfloat162*>(&h01);
            __nv_bfloat162* hp23 = reinterpret_cast<__nv_bfloat162*>(&h23);
            float l0 = v.x - __bfloat162float(hp01->x);
            float l1 = v.y - __bfloat162float(hp01->y);
            float l2 = v.z - __bfloat162float(hp23->x);
            float l3 = v.w - __bfloat162float(hp23->y);
            *reinterpret_cast<uint2*>(sAhi + row * ROW_U32 + q * 2) = make_uint2(h01, h23);
            *reinterpret_cast<uint2*>(sAlo + row * ROW_U32 + q * 2) =
                make_uint2(bf2_bits(l0, l1), bf2_bits(l2, l3));
        }
    }
    __syncthreads();

    // warp tiles: warp_m = wid&3 (32 rows -> 2 m16), warp_n = wid>>2 (64 cols -> 8 n8)
    int warp_m = wid & 3;
    int warp_n = wid >> 2;
    int lq = lane >> 2;          // 0..7
    int l4 = lane & 3;           // 0..3
    int mrow0 = warp_m * 32;
    int ncol0 = warp_n * 64;

    float acc[2][8][4];
    #pragma unroll
    for (int mt = 0; mt < 2; ++mt)
        #pragma unroll
        for (int nt = 0; nt < 8; ++nt)
            #pragma unroll
            for (int j = 0; j < 4; ++j) acc[mt][nt][j] = 0.f;

    #pragma unroll
    for (int pass = 0; pass < 3; ++pass) {
        const uint32_t* Ai = (pass == 2) ? sAlo : sAhi;
        const uint32_t* Wi = (pass == 1) ? sWlo : sWhi;
        #pragma unroll
        for (int kt = 0; kt < 8; ++kt) {
            int kc = kt * 8 + l4;                 // u32 column (= bf16 pair index)
            uint32_t a[2][4];
            #pragma unroll
            for (int mt = 0; mt < 2; ++mt) {
                int rb = (mrow0 + mt * 16 + lq) * ROW_U32;
                a[mt][0] = Ai[rb + kc];
                a[mt][1] = Ai[rb + 8 * ROW_U32 + kc];
                a[mt][2] = Ai[rb + kc + 4];
                a[mt][3] = Ai[rb + 8 * ROW_U32 + kc + 4];
            }
            #pragma unroll
            for (int nt = 0; nt < 8; ++nt) {
                int nb = (ncol0 + nt * 8 + lq) * ROW_U32;
                uint32_t b0 = Wi[nb + kc];
                uint32_t b1 = Wi[nb + kc + 4];
                mma_bf16(acc[0][nt], a[0][0], a[0][1], a[0][2], a[0][3], b0, b1);
                mma_bf16(acc[1][nt], a[1][0], a[1][1], a[1][2], a[1][3], b0, b1);
            }
        }
    }

    // epilogue
    #pragma unroll
    for (int mt = 0; mt < 2; ++mt) {
        #pragma unroll
        for (int half = 0; half < 2; ++half) {
            int r = r0 + mrow0 + mt * 16 + half * 8 + lq;
            if (r < NN) {
                #pragma unroll
                for (int nt = 0; nt < 8; ++nt) {
                    int c = ncol0 + nt * 8 + l4 * 2;
                    float2 f;
                    f.x = acc[mt][nt][half * 2 + 0];
                    f.y = acc[mt][nt][half * 2 + 1];
                    if (MODE == 1) {
                        f.x += sB2[c];
                        f.y += sB2[c + 1];
                        *(float2*)(out + (size_t)r * DD + c) = f;
                    } else {
                        *(float2*)(g_h1 + (size_t)r * DD + c) = f;
                    }
                }
            }
        }
    }
}

// ---------------- BN column stats over g_h1 ----------------
__global__ __launch_bounds__(256)
void stats_kernel() {
    int tid = threadIdx.x;
    int q = tid & 31;      // col quad
    int rt = tid >> 5;     // 0..7
    float4 s  = make_float4(0.f, 0.f, 0.f, 0.f);
    float4 sq = make_float4(0.f, 0.f, 0.f, 0.f);
    for (int r = blockIdx.x * 8 + rt; r < NN; r += 8 * 160) {
        float4 v = *(const float4*)(g_h1 + (size_t)r * DD + q * 4);
        s.x += v.x; s.y += v.y; s.z += v.z; s.w += v.w;
        sq.x += v.x * v.x; sq.y += v.y * v.y;
        sq.z += v.z * v.z; sq.w += v.w * v.w;
    }
    __shared__ float4 ss[8][32], qq[8][32];
    ss[rt][q] = s; qq[rt][q] = sq;
    __syncthreads();
    if (rt == 0) {
        #pragma unroll
        for (int i = 1; i < 8; ++i) {
            s.x += ss[i][q].x; s.y += ss[i][q].y; s.z += ss[i][q].z; s.w += ss[i][q].w;
            sq.x += qq[i][q].x; sq.y += qq[i][q].y; sq.z += qq[i][q].z; sq.w += qq[i][q].w;
        }
        atomicAdd(&g_colsum[q * 4 + 0], s.x);
        atomicAdd(&g_colsum[q * 4 + 1], s.y);
        atomicAdd(&g_colsum[q * 4 + 2], s.z);
        atomicAdd(&g_colsum[q * 4 + 3], s.w);
        atomicAdd(&g_colsq[q * 4 + 0], sq.x);
        atomicAdd(&g_colsq[q * 4 + 1], sq.y);
        atomicAdd(&g_colsq[q * 4 + 2], sq.z);
        atomicAdd(&g_colsq[q * 4 + 3], sq.w);
    }
}

// ---------------- launch ----------------
extern "C" void kernel_launch(void* const* d_in, const int* in_sizes, int n_in,
                              void* d_out, int out_size) {
    const float* x     = (const float*)d_in[0];
    const int*   src   = (const int*)  d_in[1];
    const int*   dst   = (const int*)  d_in[2];
    const float* W1    = (const float*)d_in[3];
    const float* gamma = (const float*)d_in[5];
    const float* beta  = (const float*)d_in[6];
    const float* W2    = (const float*)d_in[7];
    const float* b2    = (const float*)d_in[8];
    const float* eps   = (const float*)d_in[9];
    float*       out   = (float*)d_out;

    (void)in_sizes; (void)n_in; (void)out_size;

    cudaFuncSetAttribute(gemm_tc_kernel<0>,
                         cudaFuncAttributeMaxDynamicSharedMemorySize, GEMM_SMEM);
    cudaFuncSetAttribute(gemm_tc_kernel<1>,
                         cudaFuncAttributeMaxDynamicSharedMemorySize, GEMM_SMEM);

    prep_kernel   <<<NN * 32 / 256, 256>>>(x, W1, W2);    // 5000 blocks
    hist_kernel   <<<(EE / 8 + 255) / 256, 256>>>(dst);   // 313 blocks
    scan_kernel   <<<SCAN_BLKS, 256>>>();                 // single-pass lookback
    scatter_kernel<<<(EE / 8 + 255) / 256, 256>>>(src, dst);
    agg_kernel    <<<NN * 32 / 256, 256>>>(x, eps);

    int gblocks = (NN + 127) / 128;   // 313
    gemm_tc_kernel<0><<<gblocks, 256, GEMM_SMEM>>>(nullptr, nullptr, nullptr, nullptr);
    stats_kernel  <<<160, 256>>>();
    gemm_tc_kernel<1><<<gblocks, 256, GEMM_SMEM>>>(gamma, beta, b2, out);
}

// round 17
// speedup vs baseline: 1.3944x; 1.0124x over previous
#include <cuda_runtime.h>
#include <cuda_bf16.h>
#include <cuda_fp16.h>
#include <cstdint>

#define NN 40000
#define DD 128
#define EE 640000
#define SCAN_BLKS ((NN + 255) / 256)   // 157
#define READY (1 << 30)

// ---------------- device scratch (static, no allocation) ----------------
__device__ float    g_h  [(size_t)NN * DD];  // h = (1+eps)*x + agg
__device__ float    g_h1 [(size_t)NN * DD];  // h @ W1.T (b1 dropped: BN shift-invariant)
__device__ uint32_t g_xh [(size_t)NN * 64];  // fp16 copy of x (half2-packed)
__device__ int      g_csr[EE];
__device__ int      g_cnt[NN];
__device__ int      g_off[NN + 1];
__device__ int      g_cur[NN];
__device__ int      g_bsum[SCAN_BLKS];
__device__ float    g_colsum[DD];
__device__ float    g_colsq [DD];
// flat bf16 images per W: hi = u32[0:8192), lo = u32[8192:16384)  ([row][64] u32)
__device__ uint32_t g_w1img[16384];
__device__ uint32_t g_w2img[16384];

__device__ __forceinline__ uint32_t bf2_bits(float a, float b) {
    __nv_bfloat162 t = __floats2bfloat162_rn(a, b);
    return *reinterpret_cast<uint32_t*>(&t);
}
__device__ __forceinline__ uint32_t h2_bits(float a, float b) {
    __half2 t = __floats2half2_rn(a, b);
    return *reinterpret_cast<uint32_t*>(&t);
}

// ---------------- prep: zero counters/stats + W split + x->fp16 ----------------
__global__ __launch_bounds__(256)
void prep_kernel(const float* __restrict__ x,
                 const float* __restrict__ W1,
                 const float* __restrict__ W2) {
    int i = blockIdx.x * 256 + threadIdx.x;

    // x -> fp16 (NN*32 float4 quads)
    if (i < NN * 32) {
        int row = i >> 5, q = i & 31;
        float4 v = *(const float4*)(x + (size_t)row * DD + q * 4);
        *reinterpret_cast<uint2*>(g_xh + row * 64 + q * 2) =
            make_uint2(h2_bits(v.x, v.y), h2_bits(v.z, v.w));
    }
    if (i < NN) g_cnt[i] = 0;
    if (i < SCAN_BLKS) g_bsum[i] = 0;
    if (i < DD) { g_colsum[i] = 0.f; g_colsq[i] = 0.f; }

    // W split (8192 float4 quads across both W's)
    if (i < 8192) {
        const float* W = (i < 4096) ? W1 : W2;
        uint32_t*  img = (i < 4096) ? g_w1img : g_w2img;
        int j = i & 4095;
        int row = j >> 5, q = j & 31;
        float4 v = *(const float4*)(W + (size_t)row * DD + q * 4);
        uint32_t h01 = bf2_bits(v.x, v.y);
        uint32_t h23 = bf2_bits(v.z, v.w);
        __nv_bfloat162* hp01 = reinterpret_cast<__nv_bfloat162*>(&h01);
        __nv_bfloat162* hp23 = reinterpret_cast<__nv_bfloat162*>(&h23);
        float l0 = v.x - __bfloat162float(hp01->x);
        float l1 = v.y - __bfloat162float(hp01->y);
        float l2 = v.z - __bfloat162float(hp23->x);
        float l3 = v.w - __bfloat162float(hp23->y);
        *reinterpret_cast<uint2*>(img + row * 64 + 2 * q) = make_uint2(h01, h23);
        *reinterpret_cast<uint2*>(img + 8192 + row * 64 + 2 * q) =
            make_uint2(bf2_bits(l0, l1), bf2_bits(l2, l3));
    }
}

// ---------------- K1: histogram of dst (4 edges/thread — proven config) -------
__global__ void hist_kernel(const int* __restrict__ dst) {
    int e = (blockIdx.x * blockDim.x + threadIdx.x) * 4;
    if (e + 3 < EE) {
        int4 d = *(const int4*)(dst + e);
        atomicAdd(&g_cnt[d.x], 1);
        atomicAdd(&g_cnt[d.y], 1);
        atomicAdd(&g_cnt[d.z], 1);
        atomicAdd(&g_cnt[d.w], 1);
    }
}

// ---------------- K2: single-pass scan with decoupled lookback ----------------
__global__ __launch_bounds__(256)
void scan_kernel() {
    __shared__ int wsum[8], woff[9], pw[8], boff;
    int bid = blockIdx.x, t = threadIdx.x;
    int lane = t & 31, wrp = t >> 5;
    int i = bid * 256 + t;
    int v = (i < NN) ? g_cnt[i] : 0;

    // intra-warp inclusive scan
    int inc = v;
    #pragma unroll
    for (int o = 1; o < 32; o <<= 1) {
        int u = __shfl_up_sync(0xffffffffu, inc, o);
        if (lane >= o) inc += u;
    }
    if (lane == 31) wsum[wrp] = inc;
    __syncthreads();
    if (t == 0) {
        int r = 0;
        #pragma unroll
        for (int k = 0; k < 8; ++k) { woff[k] = r; r += wsum[k]; }
        woff[8] = r;
        atomicExch(&g_bsum[bid], r | READY);   // publish aggregate early
    }
    __syncthreads();

    // lookback: poll predecessor aggregates (<= 1 slot per thread)
    int pre = 0;
    for (int s = t; s < bid; s += 256) {
        int val;
        do { val = atomicAdd(&g_bsum[s], 0); } while (!(val & READY));
        pre += val & (READY - 1);
    }
    #pragma unroll
    for (int o = 16; o > 0; o >>= 1) pre += __shfl_down_sync(0xffffffffu, pre, o);
    if (lane == 0) pw[wrp] = pre;
    __syncthreads();
    if (t == 0) {
        int r = 0;
        #pragma unroll
        for (int k = 0; k < 8; ++k) r += pw[k];
        boff = r;
    }
    __syncthreads();

    int off = boff + woff[wrp] + (inc - v);
    if (i < NN) { g_off[i] = off; g_cur[i] = off; }
    if (bid == 0 && t == 0) g_off[NN] = EE;
}

// ---------------- K3: scatter edges into CSR (4 edges/thread — proven) --------
__global__ void scatter_kernel(const int* __restrict__ src,
                               const int* __restrict__ dst) {
    int e = (blockIdx.x * blockDim.x + threadIdx.x) * 4;
    if (e + 3 < EE) {
        int4 d = *(const int4*)(dst + e);
        int4 s = *(const int4*)(src + e);
        g_csr[atomicAdd(&g_cur[d.x], 1)] = s.x;
        g_csr[atomicAdd(&g_cur[d.y], 1)] = s.y;
        g_csr[atomicAdd(&g_cur[d.z], 1)] = s.z;
        g_csr[atomicAdd(&g_cur[d.w], 1)] = s.w;
    }
}

// ---------------- K4: aggregate (one warp per row, fp16 gather, 4-wide MLP) ----
__global__ __launch_bounds__(256)
void agg_kernel(const float* __restrict__ x, const float* __restrict__ eps) {
    int gt   = blockIdx.x * blockDim.x + threadIdx.x;
    int row  = gt >> 5;
    int lane = gt & 31;
    if (row >= NN) return;

    float s0 = 1.0f + eps[0];
    float4 a = *((const float4*)(x + (size_t)row * DD) + lane);
    a.x *= s0; a.y *= s0; a.z *= s0; a.w *= s0;

    int jb = g_off[row], je = g_off[row + 1];
    for (int j0 = jb; j0 < je; j0 += 32) {
        int rem = je - j0;
        int cnt = rem < 32 ? rem : 32;
        int myidx = (lane < cnt) ? g_csr[j0 + lane] : 0;
        int t = 0;
        for (; t + 4 <= cnt; t += 4) {
            int i0 = __shfl_sync(0xffffffffu, myidx, t);
            int i1 = __shfl_sync(0xffffffffu, myidx, t + 1);
            int i2 = __shfl_sync(0xffffffffu, myidx, t + 2);
            int i3 = __shfl_sync(0xffffffffu, myidx, t + 3);
            uint2 h0 = *((const uint2*)(g_xh + (size_t)i0 * 64) + lane);
            uint2 h1 = *((const uint2*)(g_xh + (size_t)i1 * 64) + lane);
            uint2 h2 = *((const uint2*)(g_xh + (size_t)i2 * 64) + lane);
            uint2 h3 = *((const uint2*)(g_xh + (size_t)i3 * 64) + lane);
            float2 a0 = __half22float2(*reinterpret_cast<__half2*>(&h0.x));
            float2 b0 = __half22float2(*reinterpret_cast<__half2*>(&h0.y));
            float2 a1 = __half22float2(*reinterpret_cast<__half2*>(&h1.x));
            float2 b1 = __half22float2(*reinterpret_cast<__half2*>(&h1.y));
            float2 a2 = __half22float2(*reinterpret_cast<__half2*>(&h2.x));
            float2 b2 = __half22float2(*reinterpret_cast<__half2*>(&h2.y));
            float2 a3 = __half22float2(*reinterpret_cast<__half2*>(&h3.x));
            float2 b3 = __half22float2(*reinterpret_cast<__half2*>(&h3.y));
            a.x += fmaxf(a0.x, 0.f) + fmaxf(a1.x, 0.f) + fmaxf(a2.x, 0.f) + fmaxf(a3.x, 0.f);
            a.y += fmaxf(a0.y, 0.f) + fmaxf(a1.y, 0.f) + fmaxf(a2.y, 0.f) + fmaxf(a3.y, 0.f);
            a.z += fmaxf(b0.x, 0.f) + fmaxf(b1.x, 0.f) + fmaxf(b2.x, 0.f) + fmaxf(b3.x, 0.f);
            a.w += fmaxf(b0.y, 0.f) + fmaxf(b1.y, 0.f) + fmaxf(b2.y, 0.f) + fmaxf(b3.y, 0.f);
        }
        for (; t < cnt; ++t) {
            int sidx = __shfl_sync(0xffffffffu, myidx, t);
            uint2 hv = *((const uint2*)(g_xh + (size_t)sidx * 64) + lane);
            float2 f0 = __half22float2(*reinterpret_cast<__half2*>(&hv.x));
            float2 f1 = __half22float2(*reinterpret_cast<__half2*>(&hv.y));
            a.x += fmaxf(f0.x, 0.f);
            a.y += fmaxf(f0.y, 0.f);
            a.z += fmaxf(f1.x, 0.f);
            a.w += fmaxf(f1.y, 0.f);
        }
    }
    *((float4*)(g_h + (size_t)row * DD) + lane) = a;
}

// ---------------- tensor-core GEMM via mma.sync bf16 split (3 passes) --------
// 128-row tiles, 313 blocks, 1 block/SM (proven config).
// MODE1 computes BN scale/shift per block from g_colsum/g_colsq (read-only).
#define IMG_BYTES 34816
#define ROW_U32   68
#define SB_IMG    1536
#define GEMM_SMEM (SB_IMG + 4 * IMG_BYTES)

__device__ __forceinline__ void mma_bf16(float* d, uint32_t a0, uint32_t a1,
                                         uint32_t a2, uint32_t a3,
                                         uint32_t b0, uint32_t b1) {
    asm volatile(
        "mma.sync.aligned.m16n8k16.row.col.f32.bf16.bf16.f32 "
        "{%0,%1,%2,%3}, {%4,%5,%6,%7}, {%8,%9}, {%0,%1,%2,%3};"
        : "+f"(d[0]), "+f"(d[1]), "+f"(d[2]), "+f"(d[3])
        : "r"(a0), "r"(a1), "r"(a2), "r"(a3), "r"(b0), "r"(b1));
}

template <int MODE>
__global__ __launch_bounds__(256, 1)
void gemm_tc_kernel(const float* __restrict__ gamma,
                    const float* __restrict__ beta,
                    const float* __restrict__ bias2,
                    float* __restrict__ out) {
    extern __shared__ char smem[];
    uint32_t* sAhi = (uint32_t*)(smem + SB_IMG);
    uint32_t* sAlo = (uint32_t*)(smem + SB_IMG + IMG_BYTES);
    uint32_t* sWhi = (uint32_t*)(smem + SB_IMG + 2 * IMG_BYTES);
    uint32_t* sWlo = (uint32_t*)(smem + SB_IMG + 3 * IMG_BYTES);
    float* sScale = (float*)(smem);
    float* sShift = (float*)(smem + 512);
    float* sB2    = (float*)(smem + 1024);

    int tid  = threadIdx.x;
    int wid  = tid >> 5;
    int lane = tid & 31;
    int r0   = blockIdx.x * 128;

    if (MODE == 1) {
        if (tid < DD) {
            // per-block BN finalize (redundant, read-only, L2-hot)
            float invn = 1.0f / (float)NN;
            float mu  = g_colsum[tid] * invn;
            float var = g_colsq[tid] * invn - mu * mu;
            float sc  = gamma[tid] * rsqrtf(var + 1e-5f);
            sScale[tid] = sc;
            sShift[tid] = beta[tid] - mu * sc;
            sB2[tid]    = bias2[tid];
        }
        __syncthreads();
    }

    // copy W images (hi+lo = 8192 uint2 total) into padded smem rows
    {
        const uint2* wsrc = (MODE == 0) ? (const uint2*)g_w1img : (const uint2*)g_w2img;
        #pragma unroll
        for (int it = 0; it < 32; ++it) {
            int i = it * 256 + tid;              // 0..8191 uint2
            int half = i >> 12;
            int j = i & 4095;
            int row = j >> 5, c2 = j & 31;
            uint2 v = wsrc[i];
            uint32_t* dst = half ? sWlo : sWhi;
            *reinterpret_cast<uint2*>(dst + row * ROW_U32 + c2 * 2) = v;
        }
    }

    // load + (BN-relu) + split A tile: 128 rows x 128 floats
    {
        const float* A = (MODE == 0) ? g_h : g_h1;
        #pragma unroll
        for (int it = 0; it < 16; ++it) {
            int i   = it * 256 + tid;            // 0..4095 float4
            int row = i >> 5, q = i & 31;
            int gr  = r0 + row;
            int k   = q * 4;
            float4 v;
            if (gr < NN) v = *(const float4*)(A + (size_t)gr * DD + k);
            else         v = make_float4(0.f, 0.f, 0.f, 0.f);
            if (MODE == 1) {
                v.x = fmaxf(fmaf(v.x, sScale[k + 0], sShift[k + 0]), 0.f);
                v.y = fmaxf(fmaf(v.y, sScale[k + 1], sShift[k + 1]), 0.f);
                v.z = fmaxf(fmaf(v.z, sScale[k + 2], sShift[k + 2]), 0.f);
                v.w = fmaxf(fmaf(v.w, sScale[k + 3], sShift[k + 3]), 0.f);
            }
            uint32_t h01 = bf2_bits(v.x, v.y);
            uint32_t h23 = bf2_bits(v.z, v.w);
            __nv_bfloat162* hp01 = reinterpret_cast<__nv_bfloat162*>(&h01);
            __nv_bfloat162* hp23 = reinterpret_cast<__nv_bfloat162*>(&h23);
            float l0 = v.x - __bfloat162float(hp01->x);
            float l1 = v.y - __bfloat162float(hp01->y);
            float l2 = v.z - __bfloat162float(hp23->x);
            float l3 = v.w - __bfloat162float(hp23->y);
            *reinterpret_cast<uint2*>(sAhi + row * ROW_U32 + q * 2) = make_uint2(h01, h23);
            *reinterpret_cast<uint2*>(sAlo + row * ROW_U32 + q * 2) =
                make_uint2(bf2_bits(l0, l1), bf2_bits(l2, l3));
        }
    }
    __syncthreads();

    // warp tiles: warp_m = wid&3 (32 rows -> 2 m16), warp_n = wid>>2 (64 cols -> 8 n8)
    int warp_m = wid & 3;
    int warp_n = wid >> 2;
    int lq = lane >> 2;          // 0..7
    int l4 = lane & 3;           // 0..3
    int mrow0 = warp_m * 32;
    int ncol0 = warp_n * 64;

    float acc[2][8][4];
    #pragma unroll
    for (int mt = 0; mt < 2; ++mt)
        #pragma unroll
        for (int nt = 0; nt < 8; ++nt)
            #pragma unroll
            for (int j = 0; j < 4; ++j) acc[mt][nt][j] = 0.f;

    #pragma unroll
    for (int pass = 0; pass < 3; ++pass) {
        const uint32_t* Ai = (pass == 2) ? sAlo : sAhi;
        const uint32_t* Wi = (pass == 1) ? sWlo : sWhi;
        #pragma unroll
        for (int kt = 0; kt < 8; ++kt) {
            int kc = kt * 8 + l4;                 // u32 column (= bf16 pair index)
            uint32_t a[2][4];
            #pragma unroll
            for (int mt = 0; mt < 2; ++mt) {
                int rb = (mrow0 + mt * 16 + lq) * ROW_U32;
                a[mt][0] = Ai[rb + kc];
                a[mt][1] = Ai[rb + 8 * ROW_U32 + kc];
                a[mt][2] = Ai[rb + kc + 4];
                a[mt][3] = Ai[rb + 8 * ROW_U32 + kc + 4];
            }
            #pragma unroll
            for (int nt = 0; nt < 8; ++nt) {
                int nb = (ncol0 + nt * 8 + lq) * ROW_U32;
                uint32_t b0 = Wi[nb + kc];
                uint32_t b1 = Wi[nb + kc + 4];
                mma_bf16(acc[0][nt], a[0][0], a[0][1], a[0][2], a[0][3], b0, b1);
                mma_bf16(acc[1][nt], a[1][0], a[1][1], a[1][2], a[1][3], b0, b1);
            }
        }
    }

    // epilogue
    #pragma unroll
    for (int mt = 0; mt < 2; ++mt) {
        #pragma unroll
        for (int half = 0; half < 2; ++half) {
            int r = r0 + mrow0 + mt * 16 + half * 8 + lq;
            if (r < NN) {
                #pragma unroll
                for (int nt = 0; nt < 8; ++nt) {
                    int c = ncol0 + nt * 8 + l4 * 2;
                    float2 f;
                    f.x = acc[mt][nt][half * 2 + 0];
                    f.y = acc[mt][nt][half * 2 + 1];
                    if (MODE == 1) {
                        f.x += sB2[c];
                        f.y += sB2[c + 1];
                        *(float2*)(out + (size_t)r * DD + c) = f;
                    } else {
                        *(float2*)(g_h1 + (size_t)r * DD + c) = f;
                    }
                }
            }
        }
    }
}

// ---------------- BN column stats over g_h1 ----------------
__global__ __launch_bounds__(256)
void stats_kernel() {
    int tid = threadIdx.x;
    int q = tid & 31;      // col quad
    int rt = tid >> 5;     // 0..7
    float4 s  = make_float4(0.f, 0.f, 0.f, 0.f);
    float4 sq = make_float4(0.f, 0.f, 0.f, 0.f);
    for (int r = blockIdx.x * 8 + rt; r < NN; r += 8 * 160) {
        float4 v = *(const float4*)(g_h1 + (size_t)r * DD + q * 4);
        s.x += v.x; s.y += v.y; s.z += v.z; s.w += v.w;
        sq.x += v.x * v.x; sq.y += v.y * v.y;
        sq.z += v.z * v.z; sq.w += v.w * v.w;
    }
    __shared__ float4 ss[8][32], qq[8][32];
    ss[rt][q] = s; qq[rt][q] = sq;
    __syncthreads();
    if (rt == 0) {
        #pragma unroll
        for (int i = 1; i < 8; ++i) {
            s.x += ss[i][q].x; s.y += ss[i][q].y; s.z += ss[i][q].z; s.w += ss[i][q].w;
            sq.x += qq[i][q].x; sq.y += qq[i][q].y; sq.z += qq[i][q].z; sq.w += qq[i][q].w;
        }
        atomicAdd(&g_colsum[q * 4 + 0], s.x);
        atomicAdd(&g_colsum[q * 4 + 1], s.y);
        atomicAdd(&g_colsum[q * 4 + 2], s.z);
        atomicAdd(&g_colsum[q * 4 + 3], s.w);
        atomicAdd(&g_colsq[q * 4 + 0], sq.x);
        atomicAdd(&g_colsq[q * 4 + 1], sq.y);
        atomicAdd(&g_colsq[q * 4 + 2], sq.z);
        atomicAdd(&g_colsq[q * 4 + 3], sq.w);
    }
}

// ---------------- launch ----------------
extern "C" void kernel_launch(void* const* d_in, const int* in_sizes, int n_in,
                              void* d_out, int out_size) {
    const float* x     = (const float*)d_in[0];
    const int*   src   = (const int*)  d_in[1];
    const int*   dst   = (const int*)  d_in[2];
    const float* W1    = (const float*)d_in[3];
    const float* gamma = (const float*)d_in[5];
    const float* beta  = (const float*)d_in[6];
    const float* W2    = (const float*)d_in[7];
    const float* b2    = (const float*)d_in[8];
    const float* eps   = (const float*)d_in[9];
    float*       out   = (float*)d_out;

    (void)in_sizes; (void)n_in; (void)out_size;

    cudaFuncSetAttribute(gemm_tc_kernel<0>,
                         cudaFuncAttributeMaxDynamicSharedMemorySize, GEMM_SMEM);
    cudaFuncSetAttribute(gemm_tc_kernel<1>,
                         cudaFuncAttributeMaxDynamicSharedMemorySize, GEMM_SMEM);

    prep_kernel   <<<NN * 32 / 256, 256>>>(x, W1, W2);    // 5000 blocks
    hist_kernel   <<<EE / 4 / 256, 256>>>(dst);           // 625 blocks
    scan_kernel   <<<SCAN_BLKS, 256>>>();                 // single-pass lookback
    scatter_kernel<<<EE / 4 / 256, 256>>>(src, dst);      // 625 blocks
    agg_kernel    <<<NN * 32 / 256, 256>>>(x, eps);

    int gblocks = (NN + 127) / 128;   // 313
    gemm_tc_kernel<0><<<gblocks, 256, GEMM_SMEM>>>(nullptr, nullptr, nullptr, nullptr);
    stats_kernel  <<<160, 256>>>();
    gemm_tc_kernel<1><<<gblocks, 256, GEMM_SMEM>>>(gamma, beta, b2, out);
}